// round 3
// baseline (speedup 1.0000x reference)
#include <cuda_runtime.h>

#define N_SAMPLES 16384
#define DIM       1024
#define MARGIN    1.0f
#define EPSF      1e-6f
#define BLOCK     256   // 256 threads * float4 = 1024 floats = one row

__device__ double g_acc;

__global__ void cl_init_kernel() { g_acc = 0.0; }

__global__ __launch_bounds__(BLOCK)
void cl_loss_kernel(const float* __restrict__ emb,
                    const int* __restrict__ pos_idx,
                    const int* __restrict__ neg_idx)
{
    const int i = blockIdx.x;
    const int t = threadIdx.x;
    const int warp = t >> 5;
    const int lane = t & 31;

    const int p = pos_idx[i];
    const int n = neg_idx[i];

    const float4* ra = (const float4*)(emb + (size_t)i * DIM);
    const float4* rb = (const float4*)(emb + (size_t)p * DIM);
    const float4* rc = (const float4*)(emb + (size_t)n * DIM);

    // Each thread owns one float4 from each of the three rows.
    float4 a = ra[t];
    float4 b = rb[t];
    float4 c = rc[t];

    // --- phase 1: sum of squares of each row (for the norms) ---
    float sa = a.x*a.x + a.y*a.y + a.z*a.z + a.w*a.w;
    float sb = b.x*b.x + b.y*b.y + b.z*b.z + b.w*b.w;
    float sc = c.x*c.x + c.y*c.y + c.z*c.z + c.w*c.w;

    #pragma unroll
    for (int o = 16; o > 0; o >>= 1) {
        sa += __shfl_xor_sync(0xffffffffu, sa, o);
        sb += __shfl_xor_sync(0xffffffffu, sb, o);
        sc += __shfl_xor_sync(0xffffffffu, sc, o);
    }

    __shared__ float sm[3][BLOCK / 32];
    if (lane == 0) { sm[0][warp] = sa; sm[1][warp] = sb; sm[2][warp] = sc; }
    __syncthreads();

    float ssa = 0.f, ssb = 0.f, ssc = 0.f;
    #pragma unroll
    for (int w = 0; w < BLOCK / 32; w++) {
        ssa += sm[0][w];
        ssb += sm[1][w];
        ssc += sm[2][w];
    }
    // F.normalize: x / max(||x||, eps)
    const float ia = 1.0f / fmaxf(sqrtf(ssa), EPSF);
    const float ib = 1.0f / fmaxf(sqrtf(ssb), EPSF);
    const float ic = 1.0f / fmaxf(sqrtf(ssc), EPSF);

    // --- phase 2: squared pairwise "distance" sums (note the +eps INSIDE) ---
    float dp = 0.f, dn = 0.f;
    {
        float d;
        d = a.x*ia - b.x*ib + EPSF; dp += d*d;
        d = a.y*ia - b.y*ib + EPSF; dp += d*d;
        d = a.z*ia - b.z*ib + EPSF; dp += d*d;
        d = a.w*ia - b.w*ib + EPSF; dp += d*d;

        d = a.x*ia - c.x*ic + EPSF; dn += d*d;
        d = a.y*ia - c.y*ic + EPSF; dn += d*d;
        d = a.z*ia - c.z*ic + EPSF; dn += d*d;
        d = a.w*ia - c.w*ic + EPSF; dn += d*d;
    }

    #pragma unroll
    for (int o = 16; o > 0; o >>= 1) {
        dp += __shfl_xor_sync(0xffffffffu, dp, o);
        dn += __shfl_xor_sync(0xffffffffu, dn, o);
    }

    __syncthreads();  // everyone finished reading sm from phase 1
    if (lane == 0) { sm[0][warp] = dp; sm[1][warp] = dn; }
    __syncthreads();

    if (t == 0) {
        float fdp = 0.f, fdn = 0.f;
        #pragma unroll
        for (int w = 0; w < BLOCK / 32; w++) { fdp += sm[0][w]; fdn += sm[1][w]; }

        const float d_pos = sqrtf(fdp) + EPSF;   // pairwise_distance + module eps
        const float d_neg = sqrtf(fdn) + EPSF;

        const float lp = d_pos * d_pos;
        const float tn = fmaxf(MARGIN - d_neg, EPSF);
        const float ln = tn * tn;

        atomicAdd(&g_acc, (double)(lp + ln));
    }
}

__global__ void cl_fin_kernel(float* out)
{
    out[0] = (float)(g_acc / (2.0 * (double)N_SAMPLES));
}

extern "C" void kernel_launch(void* const* d_in, const int* in_sizes, int n_in,
                              void* d_out, int out_size)
{
    const float* emb = (const float*)d_in[0];
    // d_in[1] = labels (int32) — not needed by the loss itself
    const int*   pos = (const int*)d_in[2];
    const int*   neg = (const int*)d_in[3];
    float* out = (float*)d_out;

    cl_init_kernel<<<1, 1>>>();
    cl_loss_kernel<<<N_SAMPLES, BLOCK>>>(emb, pos, neg);
    cl_fin_kernel<<<1, 1>>>(out);
}